// round 14
// baseline (speedup 1.0000x reference)
#include <cuda_runtime.h>
#include <cuda_fp16.h>
#include <cstdint>

#define SQ 2048
#define DM 1024
#define NH 16
#define HD 64
#define NT (SQ / 64)  // 32 column tiles

// All operand tensors stored as fp16x2 words (low half = even index).
__device__ float g_rsum[NH * SQ];            // per-row softmax denominators
__device__ uint32_t g_mbits[64 * SQ];        // mask bitmask, [wordcol][row]
__device__ uint32_t g_ap[3 * 256 * 4096];    // q,k,v inputs: permuted [z][mt][kt]
__device__ uint32_t g_wp[4 * 128 * 4096];    // Wq,Wk,Wv,Wo: permuted [w][nt][kt]
__device__ uint32_t g_op[256 * 4096];        // attention out O: permuted [mt][kt]
__device__ uint32_t g_qp[NH * 16 * 4096];    // Q proj (pre-scaled 1/8), per (h, mt)
__device__ uint32_t g_kp[NH * 32 * 2048];    // K proj, per (h, ttile)
__device__ uint32_t g_vp[NH * 32 * 2048];    // V^T proj, per (h, ttile)

__device__ __forceinline__ uint32_t pk(float a, float b) {
    __half2 h = __floats2half2_rn(a, b);
    return *reinterpret_cast<uint32_t*>(&h);
}

__device__ __forceinline__ void mma16(float* c, uint32_t a0, uint32_t a1, uint32_t a2,
                                      uint32_t a3, uint32_t b0, uint32_t b1) {
    asm("mma.sync.aligned.m16n8k16.row.col.f32.f16.f16.f32 "
        "{%0,%1,%2,%3},{%4,%5,%6,%7},{%8,%9},{%0,%1,%2,%3};"
        : "+f"(c[0]), "+f"(c[1]), "+f"(c[2]), "+f"(c[3])
        : "r"(a0), "r"(a1), "r"(a2), "r"(a3), "r"(b0), "r"(b1));
}

// Permuted fragment-major layout over 32-bit words (word = fp16 pair).
__device__ __forceinline__ int perm_word(int NS, int r, int k) {
    int gg = r & 7;
    int kk = k & 7;
    int L = gg * 4 + ((kk & 3) ^ (gg & 3));
    return (((r >> 4) * NS + (k >> 3)) * 32 + L) * 4 + ((r >> 3) & 1) + 2 * (kk >> 2);
}
__device__ __forceinline__ void sts_perm4(uint32_t* S, int NS, int r, int c4, uint4 u) {
    int gg = r & 7;
    int base = (((r >> 4) * NS + (c4 >> 3)) * 32 + gg * 4) * 4 + ((r >> 3) & 1) +
               2 * ((c4 >> 2) & 1);
    int x = gg & 3;
    S[base + (0 ^ x) * 4] = u.x;
    S[base + (1 ^ x) * 4] = u.y;
    S[base + (2 ^ x) * 4] = u.z;
    S[base + (3 ^ x) * 4] = u.w;
}
__device__ __forceinline__ int frag_addr(int NS, int band, int s, int g, int t4) {
    return ((band * NS + s) * 32 + g * 4 + (t4 ^ (g & 3))) * 4;
}

__device__ __forceinline__ void cpa16(void* dst, const void* src) {
    uint32_t s = (uint32_t)__cvta_generic_to_shared(dst);
    asm volatile("cp.async.cg.shared.global [%0], [%1], 16;" ::"r"(s), "l"(src));
}
#define CPA_COMMIT asm volatile("cp.async.commit_group;")
#define CPA_WAIT(n) asm volatile("cp.async.wait_group %0;" ::"n"(n))

// ---------------------------------------------------------------------------
// Pre-pass: fp16-convert + pre-permute activations (0..767) / weights
// (768..1279); mask bit-compaction (1280+).
// ---------------------------------------------------------------------------
__global__ __launch_bounds__(256) void prep(
    const float* __restrict__ q_in, const float* __restrict__ k_in,
    const float* __restrict__ v_in, const float* __restrict__ Wq,
    const float* __restrict__ Wk, const float* __restrict__ Wv,
    const float* __restrict__ Wo, const int* __restrict__ mask) {
    const int bid = blockIdx.x;
    const int tid = threadIdx.x;

    if (bid >= 1280) {
        const int lane = tid & 31, wid = tid >> 5;
        const int row = (bid - 1280) * 8 + wid;
        const int4* mp = (const int4*)(mask + (size_t)row * SQ + lane * 64);
        uint32_t w0 = 0, w1 = 0;
#pragma unroll
        for (int i = 0; i < 16; i++) {
            int4 m = mp[i];
            uint32_t bits = (m.x != 0 ? 1u : 0u) | (m.y != 0 ? 2u : 0u) |
                            (m.z != 0 ? 4u : 0u) | (m.w != 0 ? 8u : 0u);
            if (i < 8)
                w0 |= bits << (i * 4);
            else
                w1 |= bits << ((i - 8) * 4);
        }
        g_mbits[(lane * 2 + 0) * SQ + row] = w0;
        g_mbits[(lane * 2 + 1) * SQ + row] = w1;
        return;
    }

    __shared__ uint32_t sp[4096];
    const float* src;
    uint32_t* dst;
    int r0, c0;
    if (bid < 768) {
        int z = bid >> 8, rem = bid & 255;
        src = z == 0 ? q_in : z == 1 ? k_in : v_in;
        r0 = (rem >> 4) * 128;
        c0 = (rem & 15) * 64;
        dst = g_ap + (size_t)bid * 4096;
    } else {
        int wb = bid - 768;
        int w = wb >> 7, rem = wb & 127;
        src = w == 0 ? Wq : w == 1 ? Wk : w == 2 ? Wv : Wo;
        r0 = (rem >> 4) * 128;
        c0 = (rem & 15) * 64;
        dst = g_wp + (size_t)wb * 4096;
    }
#pragma unroll
    for (int i = 0; i < 4; i++) {
        int idx = tid + i * 256, r = idx >> 3, c4 = (idx & 7) * 4;
        const float* p = src + (size_t)(r0 + r) * DM + c0 + 2 * c4;
        float4 f0 = *(const float4*)p;
        float4 f1 = *(const float4*)(p + 4);
        uint4 u = {pk(f0.x, f0.y), pk(f0.z, f0.w), pk(f1.x, f1.y), pk(f1.z, f1.w)};
        sts_perm4(sp, 4, r, c4, u);
    }
    __syncthreads();
#pragma unroll
    for (int i = 0; i < 4; i++)
        *(uint4*)(dst + tid * 4 + i * 1024) = *(const uint4*)(sp + tid * 4 + i * 1024);
}

// ---------------------------------------------------------------------------
// QKV projection GEMMs (fp16). Q pre-scaled by 1/8. V -> V^T via smem bounce.
// ---------------------------------------------------------------------------
__global__ __launch_bounds__(256, 2) void gemm_qkv() {
    extern __shared__ uint32_t sm[];
    const int z = blockIdx.z, mt = blockIdx.y, nt = blockIdx.x;
    const int tid = threadIdx.x, lane = tid & 31, wid = tid >> 5;
    const int g = lane >> 2, t4 = lane & 3;
    const int wm = (wid & 1) * 64, wn = (wid >> 1) * 32;
    const uint32_t* At = g_ap + (size_t)(z * 256 + mt * 16) * 4096;
    const uint32_t* Bt = g_wp + (size_t)(z * 128 + nt * 16) * 4096;

#pragma unroll
    for (int i = 0; i < 4; i++) {
        cpa16(sm + tid * 4 + i * 1024, At + tid * 4 + i * 1024);
        cpa16(sm + 4096 + tid * 4 + i * 1024, Bt + tid * 4 + i * 1024);
    }
    CPA_COMMIT;

    float acc[4][4][4] = {};

    for (int kt = 0; kt < 16; kt++) {
        uint32_t* S = sm + (kt & 1) * 8192;
        CPA_WAIT(0);
        __syncthreads();
        if (kt + 1 < 16) {
            uint32_t* Nx = sm + ((kt + 1) & 1) * 8192;
            const uint32_t* An = At + (kt + 1) * 4096;
            const uint32_t* Bn = Bt + (kt + 1) * 4096;
#pragma unroll
            for (int i = 0; i < 4; i++) {
                cpa16(Nx + tid * 4 + i * 1024, An + tid * 4 + i * 1024);
                cpa16(Nx + 4096 + tid * 4 + i * 1024, Bn + tid * 4 + i * 1024);
            }
            CPA_COMMIT;
        }
#pragma unroll
        for (int s = 0; s < 4; s++) {
            uint4 av[4], bv[2];
#pragma unroll
            for (int mi = 0; mi < 4; mi++)
                av[mi] = *(const uint4*)&S[frag_addr(4, (wm >> 4) + mi, s, g, t4)];
#pragma unroll
            for (int bi = 0; bi < 2; bi++)
                bv[bi] = *(const uint4*)&S[4096 + frag_addr(4, (wn >> 4) + bi, s, g, t4)];
#pragma unroll
            for (int mi = 0; mi < 4; mi++)
#pragma unroll
                for (int bi = 0; bi < 2; bi++) {
                    mma16(acc[mi][bi * 2], av[mi].x, av[mi].y, av[mi].z, av[mi].w,
                          bv[bi].x, bv[bi].z);
                    mma16(acc[mi][bi * 2 + 1], av[mi].x, av[mi].y, av[mi].z, av[mi].w,
                          bv[bi].y, bv[bi].w);
                }
        }
    }

    if (z < 2) {
        const float sc = (z == 0) ? 0.125f : 1.0f;
#pragma unroll
        for (int mi = 0; mi < 4; mi++)
#pragma unroll
            for (int ni = 0; ni < 4; ni++) {
                int row = wm + mi * 16 + g;
                int colp = wn + ni * 8 + 2 * t4;
                int gn = nt * 128 + colp;
                int h = gn >> 6, kkw = (gn & 63) >> 1;
                uint32_t w0 = pk(acc[mi][ni][0] * sc, acc[mi][ni][1] * sc);
                uint32_t w1 = pk(acc[mi][ni][2] * sc, acc[mi][ni][3] * sc);
                if (z == 0) {
                    g_qp[(h * 16 + mt) * 4096 + perm_word(4, row, kkw)] = w0;
                    g_qp[(h * 16 + mt) * 4096 + perm_word(4, row + 8, kkw)] = w1;
                } else {
                    int tile = mt * 2 + (row >> 6);
                    int r64 = row & 63;
                    g_kp[(h * 32 + tile) * 2048 + perm_word(4, r64, kkw)] = w0;
                    g_kp[(h * 32 + tile) * 2048 + perm_word(4, r64 + 8, kkw)] = w1;
                }
            }
    } else {
        __syncthreads();
        __half* hb = (__half*)sm;  // [128 rows][130 halves]
#pragma unroll
        for (int mi = 0; mi < 4; mi++)
#pragma unroll
            for (int ni = 0; ni < 4; ni++) {
                int row = wm + mi * 16 + g;
                int colw = ((wn + ni * 8) >> 1) + t4;
                *(uint32_t*)&hb[row * 130 + 2 * colw] =
                    pk(acc[mi][ni][0], acc[mi][ni][1]);
                *(uint32_t*)&hb[(row + 8) * 130 + 2 * colw] =
                    pk(acc[mi][ni][2], acc[mi][ni][3]);
            }
        __syncthreads();
#pragma unroll
        for (int i = 0; i < 32; i++) {
            int widx = tid + i * 256;
            int dl = widx >> 6;
            int tw = widx & 63;
            __half lo = hb[(2 * tw) * 130 + dl];
            __half hi = hb[(2 * tw + 1) * 130 + dl];
            __half2 hh = __halves2half2(lo, hi);
            int gd = nt * 128 + dl;
            int h = gd >> 6, dr = gd & 63;
            int tt = mt * 2 + (tw >> 5), tkk = tw & 31;
            g_vp[(h * 32 + tt) * 2048 + perm_word(4, dr, tkk)] = *(uint32_t*)&hh;
        }
    }
}

// ---------------------------------------------------------------------------
// Pass 1: S = (Q/8)K^T, mask, exp -> rsum; O += S@V (pre-softmax S, register
// repack); O -> g_op; rsum -> g_rsum. NO attn stores.
// ---------------------------------------------------------------------------
__global__ __launch_bounds__(256, 2) void fused_pass1() {
    extern __shared__ uint32_t sm[];
    uint32_t* Qp = sm;           // 4096 w
    uint32_t* Kp = sm + 4096;    // 2 x 2048 w
    uint32_t* Vp = sm + 8192;    // 2 x 2048 w

    const int tid = threadIdx.x, lane = tid & 31, wid = tid >> 5;
    const int g = lane >> 2, t4 = lane & 3;
    const int h = blockIdx.y, mt = blockIdx.x;
    const int m0 = mt * 128;
    const int r0 = wid * 16 + g;
    const uint32_t* kg = g_kp + h * 32 * 2048;
    const uint32_t* vg = g_vp + h * 32 * 2048;

    {
        const uint32_t* qg = g_qp + (h * 16 + mt) * 4096;
#pragma unroll
        for (int i = 0; i < 4; i++)
            cpa16(Qp + tid * 4 + i * 1024, qg + tid * 4 + i * 1024);
    }
#pragma unroll
    for (int i = 0; i < 2; i++) {
        cpa16(Kp + tid * 4 + i * 1024, kg + tid * 4 + i * 1024);
        cpa16(Vp + tid * 4 + i * 1024, vg + tid * 4 + i * 1024);
    }
    CPA_COMMIT;
    CPA_WAIT(0);
    __syncthreads();

    uint4 qf[4];
#pragma unroll
    for (int s = 0; s < 4; s++)
        qf[s] = *(const uint4*)&Qp[frag_addr(4, wid, s, g, t4)];

    float oacc[8][4] = {};
    float rsum[2] = {};

    for (int tt = 0; tt < NT; tt++) {
        uint32_t* Kc = Kp + (tt & 1) * 2048;
        uint32_t* Vc = Vp + (tt & 1) * 2048;

        uint32_t mw[2][2];
        {
            const uint32_t* mb = g_mbits + (size_t)(tt * 2) * SQ + m0;
            mw[0][0] = mb[r0];
            mw[0][1] = mb[SQ + r0];
            mw[1][0] = mb[r0 + 8];
            mw[1][1] = mb[SQ + r0 + 8];
        }

        if (tt + 1 < NT) {
            uint32_t* Kn = Kp + ((tt + 1) & 1) * 2048;
            uint32_t* Vn = Vp + ((tt + 1) & 1) * 2048;
#pragma unroll
            for (int i = 0; i < 2; i++) {
                cpa16(Kn + tid * 4 + i * 1024,
                      kg + (tt + 1) * 2048 + tid * 4 + i * 1024);
                cpa16(Vn + tid * 4 + i * 1024,
                      vg + (tt + 1) * 2048 + tid * 4 + i * 1024);
            }
            CPA_COMMIT;
        }

        float sacc[8][4] = {};
#pragma unroll
        for (int s = 0; s < 4; s++) {
#pragma unroll
            for (int b = 0; b < 4; b++) {
                uint4 bk = *(const uint4*)&Kc[frag_addr(4, b, s, g, t4)];
                mma16(sacc[b * 2], qf[s].x, qf[s].y, qf[s].z, qf[s].w, bk.x, bk.z);
                mma16(sacc[b * 2 + 1], qf[s].x, qf[s].y, qf[s].z, qf[s].w, bk.y, bk.w);
            }
        }

        uint4 av[4];
#pragma unroll
        for (int ni = 0; ni < 8; ni++) {
            int cl = ni * 8 + 2 * t4;
            int word = ni >> 2, bit = cl & 31;
            float v00 = sacc[ni][0], v01 = sacc[ni][1];
            float v10 = sacc[ni][2], v11 = sacc[ni][3];
            uint32_t w0 = mw[0][word], w1 = mw[1][word];
            if ((w0 >> bit) & 1) v00 = -1e-7f;
            if ((w0 >> (bit + 1)) & 1) v01 = -1e-7f;
            if ((w1 >> bit) & 1) v10 = -1e-7f;
            if ((w1 >> (bit + 1)) & 1) v11 = -1e-7f;
            rsum[0] += __expf(v00) + __expf(v01);
            rsum[1] += __expf(v10) + __expf(v11);
            uint32_t plo = pk(v00, v01), phi = pk(v10, v11);
            if ((ni & 1) == 0) {
                av[ni >> 1].x = plo;
                av[ni >> 1].y = phi;
            } else {
                av[ni >> 1].z = plo;
                av[ni >> 1].w = phi;
            }
        }

#pragma unroll
        for (int s = 0; s < 4; s++) {
#pragma unroll
            for (int b = 0; b < 4; b++) {
                uint4 bv = *(const uint4*)&Vc[frag_addr(4, b, s, g, t4)];
                mma16(oacc[b * 2], av[s].x, av[s].y, av[s].z, av[s].w, bv.x, bv.z);
                mma16(oacc[b * 2 + 1], av[s].x, av[s].y, av[s].z, av[s].w, bv.y, bv.w);
            }
        }

        if (tt + 1 < NT) {
            CPA_WAIT(0);
            __syncthreads();
        }
    }

#pragma unroll
    for (int di = 0; di < 8; di++) {
        int lk = di * 4 + t4;
        g_op[(mt * 16 + h) * 4096 + perm_word(4, r0, lk)] =
            pk(oacc[di][0], oacc[di][1]);
        g_op[(mt * 16 + h) * 4096 + perm_word(4, r0 + 8, lk)] =
            pk(oacc[di][2], oacc[di][3]);
    }

    rsum[0] += __shfl_xor_sync(0xffffffffu, rsum[0], 1);
    rsum[0] += __shfl_xor_sync(0xffffffffu, rsum[0], 2);
    rsum[1] += __shfl_xor_sync(0xffffffffu, rsum[1], 1);
    rsum[1] += __shfl_xor_sync(0xffffffffu, rsum[1], 2);
    if (t4 == 0) {
        g_rsum[h * SQ + m0 + r0] = rsum[0];
        g_rsum[h * SQ + m0 + r0 + 8] = rsum[1];
    }
}

// ---------------------------------------------------------------------------
// Heterogeneous pass 2 at 3 CTAs/SM. Blocks 0..255 = output projection with
// BM=128 x BN=64 (acc 32 regs, 48KB smem). Blocks 256..767 = attn
// recompute+normalize writers (32KB smem), each (h, mt, half-column-range).
// ---------------------------------------------------------------------------
__global__ __launch_bounds__(256, 3) void pass2(float* __restrict__ C,
                                                float* __restrict__ attn) {
    extern __shared__ uint32_t sm[];
    const int bid = blockIdx.x;
    const int tid = threadIdx.x;
    const int lane = tid & 31, wid = tid >> 5;
    const int g = lane >> 2, t4 = lane & 3;

    if (bid >= 256) {  // attn writers: 512 blocks = (h, mt, half)
        const int pb = bid - 256;
        const int half = pb & 1;
        const int pb2 = pb >> 1;
        const int h = pb2 >> 4, mt = pb2 & 15;
        const int m0 = mt * 128;
        const int r0 = wid * 16 + g;
        const int tt0 = half * (NT / 2), tt1 = tt0 + NT / 2;
        const size_t attn_base = (size_t)h * SQ * SQ;
        const uint32_t* kg = g_kp + h * 32 * 2048;
        uint32_t* Qp = sm;         // 4096 w
        uint32_t* Kp = sm + 4096;  // 2 x 2048 w

        {
            const uint32_t* qg = g_qp + (h * 16 + mt) * 4096;
#pragma unroll
            for (int i = 0; i < 4; i++)
                cpa16(Qp + tid * 4 + i * 1024, qg + tid * 4 + i * 1024);
        }
#pragma unroll
        for (int i = 0; i < 2; i++)
            cpa16(Kp + tid * 4 + i * 1024, kg + tt0 * 2048 + tid * 4 + i * 1024);
        CPA_COMMIT;
        CPA_WAIT(0);
        __syncthreads();

        uint4 qf[4];
#pragma unroll
        for (int s = 0; s < 4; s++)
            qf[s] = *(const uint4*)&Qp[frag_addr(4, wid, s, g, t4)];

        const float inv0 = 1.0f / g_rsum[h * SQ + m0 + r0];
        const float inv1 = 1.0f / g_rsum[h * SQ + m0 + r0 + 8];

        for (int tt = tt0; tt < tt1; tt++) {
            const int t0 = tt * 64;
            uint32_t* Kc = Kp + (tt & 1) * 2048;

            uint32_t mw[2][2];
            {
                const uint32_t* mb = g_mbits + (size_t)(tt * 2) * SQ + m0;
                mw[0][0] = mb[r0];
                mw[0][1] = mb[SQ + r0];
                mw[1][0] = mb[r0 + 8];
                mw[1][1] = mb[SQ + r0 + 8];
            }

            if (tt + 1 < tt1) {
                uint32_t* Kn = Kp + ((tt + 1) & 1) * 2048;
#pragma unroll
                for (int i = 0; i < 2; i++)
                    cpa16(Kn + tid * 4 + i * 1024,
                          kg + (tt + 1) * 2048 + tid * 4 + i * 1024);
                CPA_COMMIT;
            }

            float sacc[8][4] = {};
#pragma unroll
            for (int s = 0; s < 4; s++) {
#pragma unroll
                for (int b = 0; b < 4; b++) {
                    uint4 bk = *(const uint4*)&Kc[frag_addr(4, b, s, g, t4)];
                    mma16(sacc[b * 2], qf[s].x, qf[s].y, qf[s].z, qf[s].w, bk.x, bk.z);
                    mma16(sacc[b * 2 + 1], qf[s].x, qf[s].y, qf[s].z, qf[s].w, bk.y,
                          bk.w);
                }
            }

#pragma unroll
            for (int ni = 0; ni < 8; ni++) {
                int cl = ni * 8 + 2 * t4;
                int word = ni >> 2, bit = cl & 31;
                float v00 = sacc[ni][0], v01 = sacc[ni][1];
                float v10 = sacc[ni][2], v11 = sacc[ni][3];
                uint32_t w0 = mw[0][word], w1 = mw[1][word];
                if ((w0 >> bit) & 1) v00 = -1e-7f;
                if ((w0 >> (bit + 1)) & 1) v01 = -1e-7f;
                if ((w1 >> bit) & 1) v10 = -1e-7f;
                if ((w1 >> (bit + 1)) & 1) v11 = -1e-7f;
                size_t cg = attn_base + (size_t)(m0 + r0) * SQ + t0 + cl;
                __stcs((float2*)(attn + cg),
                       make_float2(__expf(v00) * inv0, __expf(v01) * inv0));
                __stcs((float2*)(attn + cg + 8 * SQ),
                       make_float2(__expf(v10) * inv1, __expf(v11) * inv1));
            }

            if (tt + 1 < tt1) {
                CPA_WAIT(0);
                __syncthreads();
            }
        }
        return;
    }

    // output projection: BM=128, BN=64. block = (mt 0..15, nt 0..15)
    const int mt = bid >> 4, nt = bid & 15;
    const int wm = (wid & 1) * 64, wn = (wid >> 1) * 16;
    const uint32_t* At = g_op + (size_t)(mt * 16) * 4096;
    const uint32_t* Bt = g_wp + (size_t)(3 * 128 + (nt >> 1) * 16) * 4096 +
                         (nt & 1) * 2048;  // 64-row half of the weight tile

#pragma unroll
    for (int i = 0; i < 4; i++)
        cpa16(sm + tid * 4 + i * 1024, At + tid * 4 + i * 1024);
#pragma unroll
    for (int i = 0; i < 2; i++)
        cpa16(sm + 4096 + tid * 4 + i * 1024, Bt + tid * 4 + i * 1024);
    CPA_COMMIT;

    float acc[4][2][4] = {};

    for (int kt = 0; kt < 16; kt++) {
        uint32_t* S = sm + (kt & 1) * 6144;  // stage: A 4096 | B 2048
        CPA_WAIT(0);
        __syncthreads();
        if (kt + 1 < 16) {
            uint32_t* Nx = sm + ((kt + 1) & 1) * 6144;
            const uint32_t* An = At + (kt + 1) * 4096;
            const uint32_t* Bn = Bt + (kt + 1) * 4096;
#pragma unroll
            for (int i = 0; i < 4; i++)
                cpa16(Nx + tid * 4 + i * 1024, An + tid * 4 + i * 1024);
#pragma unroll
            for (int i = 0; i < 2; i++)
                cpa16(Nx + 4096 + tid * 4 + i * 1024, Bn + tid * 4 + i * 1024);
            CPA_COMMIT;
        }
#pragma unroll
        for (int s = 0; s < 4; s++) {
            uint4 av[4];
#pragma unroll
            for (int mi = 0; mi < 4; mi++)
                av[mi] = *(const uint4*)&S[frag_addr(4, (wm >> 4) + mi, s, g, t4)];
            uint4 bv = *(const uint4*)&S[4096 + frag_addr(4, wn >> 4, s, g, t4)];
#pragma unroll
            for (int mi = 0; mi < 4; mi++) {
                mma16(acc[mi][0], av[mi].x, av[mi].y, av[mi].z, av[mi].w, bv.x, bv.z);
                mma16(acc[mi][1], av[mi].x, av[mi].y, av[mi].z, av[mi].w, bv.y, bv.w);
            }
        }
    }

#pragma unroll
    for (int mi = 0; mi < 4; mi++)
#pragma unroll
        for (int ni = 0; ni < 2; ni++)
#pragma unroll
            for (int e = 0; e < 4; e++) {
                int row = mt * 128 + wm + mi * 16 + g + (e >> 1) * 8;
                int col = nt * 64 + wn + ni * 8 + t4 * 2 + (e & 1);
                C[(size_t)row * DM + col] = acc[mi][ni][e];
            }
}

extern "C" void kernel_launch(void* const* d_in, const int* in_sizes, int n_in,
                              void* d_out, int out_size) {
    const float* q_in = (const float*)d_in[0];
    const float* k_in = (const float*)d_in[1];
    const float* v_in = (const float*)d_in[2];
    const int* mask = (const int*)d_in[3];
    const float* Wq = (const float*)d_in[4];
    const float* Wk = (const float*)d_in[5];
    const float* Wv = (const float*)d_in[6];
    const float* Wo = (const float*)d_in[7];

    float* out = (float*)d_out;           // [S, DM]
    float* attn = out + (size_t)SQ * DM;  // [H, S, S]

    static int smem_set = 0;
    if (!smem_set) {
        cudaFuncSetAttribute(fused_pass1, cudaFuncAttributeMaxDynamicSharedMemorySize,
                             49152);
        cudaFuncSetAttribute(gemm_qkv, cudaFuncAttributeMaxDynamicSharedMemorySize,
                             65536);
        cudaFuncSetAttribute(pass2, cudaFuncAttributeMaxDynamicSharedMemorySize,
                             49152);
        smem_set = 1;
    }

    prep<<<1536, 256>>>(q_in, k_in, v_in, Wq, Wk, Wv, Wo, mask);

    dim3 gQKV(8, 16, 3);
    gemm_qkv<<<gQKV, 256, 65536>>>();

    dim3 gFused(SQ / 128, NH, 1);  // (16, 16)
    fused_pass1<<<gFused, 256, 49152>>>();

    pass2<<<256 + 512, 256, 49152>>>(out, attn);
}

// round 15
// speedup vs baseline: 1.0507x; 1.0507x over previous
#include <cuda_runtime.h>
#include <cuda_fp16.h>
#include <cstdint>

#define SQ 2048
#define DM 1024
#define NH 16
#define HD 64
#define NT (SQ / 64)  // 32 column tiles

// All operand tensors stored as fp16x2 words (low half = even index).
__device__ float g_rsum[NH * SQ];            // per-row softmax denominators
__device__ uint32_t g_mbits[64 * SQ];        // mask bitmask, [wordcol][row]
__device__ uint32_t g_ap[3 * 256 * 4096];    // q,k,v inputs: permuted [z][mt][kt]
__device__ uint32_t g_wp[4 * 128 * 4096];    // Wq,Wk,Wv,Wo: permuted [w][nt][kt]
__device__ uint32_t g_op[256 * 4096];        // attention out O: permuted [mt][kt]
__device__ uint32_t g_qp[NH * 16 * 4096];    // Q proj (pre-scaled 1/8), per (h, mt)
__device__ uint32_t g_kp[NH * 32 * 2048];    // K proj, per (h, ttile)
__device__ uint32_t g_vp[NH * 32 * 2048];    // V^T proj, per (h, ttile)

__device__ __forceinline__ uint32_t pk(float a, float b) {
    __half2 h = __floats2half2_rn(a, b);
    return *reinterpret_cast<uint32_t*>(&h);
}

// exp of an fp16 pair in ONE MUFU op: ex2.approx.f16x2(x * log2e).
__device__ __forceinline__ float2 h2exp_f2(uint32_t v) {
    __half2 h = *reinterpret_cast<__half2*>(&v);
    h = __hmul2(h, __float2half2_rn(1.4426950408889634f));
    uint32_t u = *reinterpret_cast<uint32_t*>(&h);
    asm("ex2.approx.f16x2 %0, %0;" : "+r"(u));
    return __half22float2(*reinterpret_cast<__half2*>(&u));
}

__device__ __forceinline__ void mma16(float* c, uint32_t a0, uint32_t a1, uint32_t a2,
                                      uint32_t a3, uint32_t b0, uint32_t b1) {
    asm("mma.sync.aligned.m16n8k16.row.col.f32.f16.f16.f32 "
        "{%0,%1,%2,%3},{%4,%5,%6,%7},{%8,%9},{%0,%1,%2,%3};"
        : "+f"(c[0]), "+f"(c[1]), "+f"(c[2]), "+f"(c[3])
        : "r"(a0), "r"(a1), "r"(a2), "r"(a3), "r"(b0), "r"(b1));
}

// Permuted fragment-major layout over 32-bit words (word = fp16 pair).
__device__ __forceinline__ int perm_word(int NS, int r, int k) {
    int gg = r & 7;
    int kk = k & 7;
    int L = gg * 4 + ((kk & 3) ^ (gg & 3));
    return (((r >> 4) * NS + (k >> 3)) * 32 + L) * 4 + ((r >> 3) & 1) + 2 * (kk >> 2);
}
__device__ __forceinline__ void sts_perm4(uint32_t* S, int NS, int r, int c4, uint4 u) {
    int gg = r & 7;
    int base = (((r >> 4) * NS + (c4 >> 3)) * 32 + gg * 4) * 4 + ((r >> 3) & 1) +
               2 * ((c4 >> 2) & 1);
    int x = gg & 3;
    S[base + (0 ^ x) * 4] = u.x;
    S[base + (1 ^ x) * 4] = u.y;
    S[base + (2 ^ x) * 4] = u.z;
    S[base + (3 ^ x) * 4] = u.w;
}
__device__ __forceinline__ int frag_addr(int NS, int band, int s, int g, int t4) {
    return ((band * NS + s) * 32 + g * 4 + (t4 ^ (g & 3))) * 4;
}

__device__ __forceinline__ void cpa16(void* dst, const void* src) {
    uint32_t s = (uint32_t)__cvta_generic_to_shared(dst);
    asm volatile("cp.async.cg.shared.global [%0], [%1], 16;" ::"r"(s), "l"(src));
}
#define CPA_COMMIT asm volatile("cp.async.commit_group;")
#define CPA_WAIT(n) asm volatile("cp.async.wait_group %0;" ::"n"(n))

// ---------------------------------------------------------------------------
// Pre-pass: fp16-convert + pre-permute activations (0..767) / weights
// (768..1279); mask bit-compaction (1280+).
// ---------------------------------------------------------------------------
__global__ __launch_bounds__(256) void prep(
    const float* __restrict__ q_in, const float* __restrict__ k_in,
    const float* __restrict__ v_in, const float* __restrict__ Wq,
    const float* __restrict__ Wk, const float* __restrict__ Wv,
    const float* __restrict__ Wo, const int* __restrict__ mask) {
    const int bid = blockIdx.x;
    const int tid = threadIdx.x;

    if (bid >= 1280) {
        const int lane = tid & 31, wid = tid >> 5;
        const int row = (bid - 1280) * 8 + wid;
        const int4* mp = (const int4*)(mask + (size_t)row * SQ + lane * 64);
        uint32_t w0 = 0, w1 = 0;
#pragma unroll
        for (int i = 0; i < 16; i++) {
            int4 m = mp[i];
            uint32_t bits = (m.x != 0 ? 1u : 0u) | (m.y != 0 ? 2u : 0u) |
                            (m.z != 0 ? 4u : 0u) | (m.w != 0 ? 8u : 0u);
            if (i < 8)
                w0 |= bits << (i * 4);
            else
                w1 |= bits << ((i - 8) * 4);
        }
        g_mbits[(lane * 2 + 0) * SQ + row] = w0;
        g_mbits[(lane * 2 + 1) * SQ + row] = w1;
        return;
    }

    __shared__ uint32_t sp[4096];
    const float* src;
    uint32_t* dst;
    int r0, c0;
    if (bid < 768) {
        int z = bid >> 8, rem = bid & 255;
        src = z == 0 ? q_in : z == 1 ? k_in : v_in;
        r0 = (rem >> 4) * 128;
        c0 = (rem & 15) * 64;
        dst = g_ap + (size_t)bid * 4096;
    } else {
        int wb = bid - 768;
        int w = wb >> 7, rem = wb & 127;
        src = w == 0 ? Wq : w == 1 ? Wk : w == 2 ? Wv : Wo;
        r0 = (rem >> 4) * 128;
        c0 = (rem & 15) * 64;
        dst = g_wp + (size_t)wb * 4096;
    }
#pragma unroll
    for (int i = 0; i < 4; i++) {
        int idx = tid + i * 256, r = idx >> 3, c4 = (idx & 7) * 4;
        const float* p = src + (size_t)(r0 + r) * DM + c0 + 2 * c4;
        float4 f0 = *(const float4*)p;
        float4 f1 = *(const float4*)(p + 4);
        uint4 u = {pk(f0.x, f0.y), pk(f0.z, f0.w), pk(f1.x, f1.y), pk(f1.z, f1.w)};
        sts_perm4(sp, 4, r, c4, u);
    }
    __syncthreads();
#pragma unroll
    for (int i = 0; i < 4; i++)
        *(uint4*)(dst + tid * 4 + i * 1024) = *(const uint4*)(sp + tid * 4 + i * 1024);
}

// ---------------------------------------------------------------------------
// QKV projection GEMMs (fp16). Q pre-scaled by 1/8. V -> V^T via smem bounce.
// ---------------------------------------------------------------------------
__global__ __launch_bounds__(256, 2) void gemm_qkv() {
    extern __shared__ uint32_t sm[];
    const int z = blockIdx.z, mt = blockIdx.y, nt = blockIdx.x;
    const int tid = threadIdx.x, lane = tid & 31, wid = tid >> 5;
    const int g = lane >> 2, t4 = lane & 3;
    const int wm = (wid & 1) * 64, wn = (wid >> 1) * 32;
    const uint32_t* At = g_ap + (size_t)(z * 256 + mt * 16) * 4096;
    const uint32_t* Bt = g_wp + (size_t)(z * 128 + nt * 16) * 4096;

#pragma unroll
    for (int i = 0; i < 4; i++) {
        cpa16(sm + tid * 4 + i * 1024, At + tid * 4 + i * 1024);
        cpa16(sm + 4096 + tid * 4 + i * 1024, Bt + tid * 4 + i * 1024);
    }
    CPA_COMMIT;

    float acc[4][4][4] = {};

    for (int kt = 0; kt < 16; kt++) {
        uint32_t* S = sm + (kt & 1) * 8192;
        CPA_WAIT(0);
        __syncthreads();
        if (kt + 1 < 16) {
            uint32_t* Nx = sm + ((kt + 1) & 1) * 8192;
            const uint32_t* An = At + (kt + 1) * 4096;
            const uint32_t* Bn = Bt + (kt + 1) * 4096;
#pragma unroll
            for (int i = 0; i < 4; i++) {
                cpa16(Nx + tid * 4 + i * 1024, An + tid * 4 + i * 1024);
                cpa16(Nx + 4096 + tid * 4 + i * 1024, Bn + tid * 4 + i * 1024);
            }
            CPA_COMMIT;
        }
#pragma unroll
        for (int s = 0; s < 4; s++) {
            uint4 av[4], bv[2];
#pragma unroll
            for (int mi = 0; mi < 4; mi++)
                av[mi] = *(const uint4*)&S[frag_addr(4, (wm >> 4) + mi, s, g, t4)];
#pragma unroll
            for (int bi = 0; bi < 2; bi++)
                bv[bi] = *(const uint4*)&S[4096 + frag_addr(4, (wn >> 4) + bi, s, g, t4)];
#pragma unroll
            for (int mi = 0; mi < 4; mi++)
#pragma unroll
                for (int bi = 0; bi < 2; bi++) {
                    mma16(acc[mi][bi * 2], av[mi].x, av[mi].y, av[mi].z, av[mi].w,
                          bv[bi].x, bv[bi].z);
                    mma16(acc[mi][bi * 2 + 1], av[mi].x, av[mi].y, av[mi].z, av[mi].w,
                          bv[bi].y, bv[bi].w);
                }
        }
    }

    if (z < 2) {
        const float sc = (z == 0) ? 0.125f : 1.0f;
#pragma unroll
        for (int mi = 0; mi < 4; mi++)
#pragma unroll
            for (int ni = 0; ni < 4; ni++) {
                int row = wm + mi * 16 + g;
                int colp = wn + ni * 8 + 2 * t4;
                int gn = nt * 128 + colp;
                int h = gn >> 6, kkw = (gn & 63) >> 1;
                uint32_t w0 = pk(acc[mi][ni][0] * sc, acc[mi][ni][1] * sc);
                uint32_t w1 = pk(acc[mi][ni][2] * sc, acc[mi][ni][3] * sc);
                if (z == 0) {
                    g_qp[(h * 16 + mt) * 4096 + perm_word(4, row, kkw)] = w0;
                    g_qp[(h * 16 + mt) * 4096 + perm_word(4, row + 8, kkw)] = w1;
                } else {
                    int tile = mt * 2 + (row >> 6);
                    int r64 = row & 63;
                    g_kp[(h * 32 + tile) * 2048 + perm_word(4, r64, kkw)] = w0;
                    g_kp[(h * 32 + tile) * 2048 + perm_word(4, r64 + 8, kkw)] = w1;
                }
            }
    } else {
        __syncthreads();
        __half* hb = (__half*)sm;  // [128 rows][130 halves]
#pragma unroll
        for (int mi = 0; mi < 4; mi++)
#pragma unroll
            for (int ni = 0; ni < 4; ni++) {
                int row = wm + mi * 16 + g;
                int colw = ((wn + ni * 8) >> 1) + t4;
                *(uint32_t*)&hb[row * 130 + 2 * colw] =
                    pk(acc[mi][ni][0], acc[mi][ni][1]);
                *(uint32_t*)&hb[(row + 8) * 130 + 2 * colw] =
                    pk(acc[mi][ni][2], acc[mi][ni][3]);
            }
        __syncthreads();
#pragma unroll
        for (int i = 0; i < 32; i++) {
            int widx = tid + i * 256;
            int dl = widx >> 6;
            int tw = widx & 63;
            __half lo = hb[(2 * tw) * 130 + dl];
            __half hi = hb[(2 * tw + 1) * 130 + dl];
            __half2 hh = __halves2half2(lo, hi);
            int gd = nt * 128 + dl;
            int h = gd >> 6, dr = gd & 63;
            int tt = mt * 2 + (tw >> 5), tkk = tw & 31;
            g_vp[(h * 32 + tt) * 2048 + perm_word(4, dr, tkk)] = *(uint32_t*)&hh;
        }
    }
}

// ---------------------------------------------------------------------------
// Pass 1: S = (Q/8)K^T, mask -> rsum via fp16x2 exp (ONE MUFU per pair);
// O += S@V (pre-softmax S, register repack); O -> g_op; rsum -> g_rsum.
// NO attn stores.
// ---------------------------------------------------------------------------
__global__ __launch_bounds__(256, 2) void fused_pass1() {
    extern __shared__ uint32_t sm[];
    uint32_t* Qp = sm;           // 4096 w
    uint32_t* Kp = sm + 4096;    // 2 x 2048 w
    uint32_t* Vp = sm + 8192;    // 2 x 2048 w

    const int tid = threadIdx.x, lane = tid & 31, wid = tid >> 5;
    const int g = lane >> 2, t4 = lane & 3;
    const int h = blockIdx.y, mt = blockIdx.x;
    const int m0 = mt * 128;
    const int r0 = wid * 16 + g;
    const uint32_t* kg = g_kp + h * 32 * 2048;
    const uint32_t* vg = g_vp + h * 32 * 2048;

    {
        const uint32_t* qg = g_qp + (h * 16 + mt) * 4096;
#pragma unroll
        for (int i = 0; i < 4; i++)
            cpa16(Qp + tid * 4 + i * 1024, qg + tid * 4 + i * 1024);
    }
#pragma unroll
    for (int i = 0; i < 2; i++) {
        cpa16(Kp + tid * 4 + i * 1024, kg + tid * 4 + i * 1024);
        cpa16(Vp + tid * 4 + i * 1024, vg + tid * 4 + i * 1024);
    }
    CPA_COMMIT;
    CPA_WAIT(0);
    __syncthreads();

    uint4 qf[4];
#pragma unroll
    for (int s = 0; s < 4; s++)
        qf[s] = *(const uint4*)&Qp[frag_addr(4, wid, s, g, t4)];

    float oacc[8][4] = {};
    float rsum[2] = {};

    for (int tt = 0; tt < NT; tt++) {
        uint32_t* Kc = Kp + (tt & 1) * 2048;
        uint32_t* Vc = Vp + (tt & 1) * 2048;

        uint32_t mw[2][2];
        {
            const uint32_t* mb = g_mbits + (size_t)(tt * 2) * SQ + m0;
            mw[0][0] = mb[r0];
            mw[0][1] = mb[SQ + r0];
            mw[1][0] = mb[r0 + 8];
            mw[1][1] = mb[SQ + r0 + 8];
        }

        if (tt + 1 < NT) {
            uint32_t* Kn = Kp + ((tt + 1) & 1) * 2048;
            uint32_t* Vn = Vp + ((tt + 1) & 1) * 2048;
#pragma unroll
            for (int i = 0; i < 2; i++) {
                cpa16(Kn + tid * 4 + i * 1024,
                      kg + (tt + 1) * 2048 + tid * 4 + i * 1024);
                cpa16(Vn + tid * 4 + i * 1024,
                      vg + (tt + 1) * 2048 + tid * 4 + i * 1024);
            }
            CPA_COMMIT;
        }

        float sacc[8][4] = {};
#pragma unroll
        for (int s = 0; s < 4; s++) {
#pragma unroll
            for (int b = 0; b < 4; b++) {
                uint4 bk = *(const uint4*)&Kc[frag_addr(4, b, s, g, t4)];
                mma16(sacc[b * 2], qf[s].x, qf[s].y, qf[s].z, qf[s].w, bk.x, bk.z);
                mma16(sacc[b * 2 + 1], qf[s].x, qf[s].y, qf[s].z, qf[s].w, bk.y, bk.w);
            }
        }

        uint4 av[4];
#pragma unroll
        for (int ni = 0; ni < 8; ni++) {
            int cl = ni * 8 + 2 * t4;
            int word = ni >> 2, bit = cl & 31;
            float v00 = sacc[ni][0], v01 = sacc[ni][1];
            float v10 = sacc[ni][2], v11 = sacc[ni][3];
            uint32_t w0 = mw[0][word], w1 = mw[1][word];
            if ((w0 >> bit) & 1) v00 = -1e-7f;
            if ((w0 >> (bit + 1)) & 1) v01 = -1e-7f;
            if ((w1 >> bit) & 1) v10 = -1e-7f;
            if ((w1 >> (bit + 1)) & 1) v11 = -1e-7f;
            uint32_t plo = pk(v00, v01), phi = pk(v10, v11);
            float2 e0 = h2exp_f2(plo);
            float2 e1 = h2exp_f2(phi);
            rsum[0] += e0.x + e0.y;
            rsum[1] += e1.x + e1.y;
            if ((ni & 1) == 0) {
                av[ni >> 1].x = plo;
                av[ni >> 1].y = phi;
            } else {
                av[ni >> 1].z = plo;
                av[ni >> 1].w = phi;
            }
        }

#pragma unroll
        for (int s = 0; s < 4; s++) {
#pragma unroll
            for (int b = 0; b < 4; b++) {
                uint4 bv = *(const uint4*)&Vc[frag_addr(4, b, s, g, t4)];
                mma16(oacc[b * 2], av[s].x, av[s].y, av[s].z, av[s].w, bv.x, bv.z);
                mma16(oacc[b * 2 + 1], av[s].x, av[s].y, av[s].z, av[s].w, bv.y, bv.w);
            }
        }

        if (tt + 1 < NT) {
            CPA_WAIT(0);
            __syncthreads();
        }
    }

#pragma unroll
    for (int di = 0; di < 8; di++) {
        int lk = di * 4 + t4;
        g_op[(mt * 16 + h) * 4096 + perm_word(4, r0, lk)] =
            pk(oacc[di][0], oacc[di][1]);
        g_op[(mt * 16 + h) * 4096 + perm_word(4, r0 + 8, lk)] =
            pk(oacc[di][2], oacc[di][3]);
    }

    rsum[0] += __shfl_xor_sync(0xffffffffu, rsum[0], 1);
    rsum[0] += __shfl_xor_sync(0xffffffffu, rsum[0], 2);
    rsum[1] += __shfl_xor_sync(0xffffffffu, rsum[1], 1);
    rsum[1] += __shfl_xor_sync(0xffffffffu, rsum[1], 2);
    if (t4 == 0) {
        g_rsum[h * SQ + m0 + r0] = rsum[0];
        g_rsum[h * SQ + m0 + r0 + 8] = rsum[1];
    }
}

// ---------------------------------------------------------------------------
// Heterogeneous pass 2 (round-12 shape): blocks 0..127 = output projection
// (BM=128 x BN=128 cp.async GEMM); blocks 128..383 = attn recompute+normalize
// writers (full column range, fp32 exp for stored probabilities).
// ---------------------------------------------------------------------------
__global__ __launch_bounds__(256, 2) void pass2(float* __restrict__ C,
                                                float* __restrict__ attn) {
    extern __shared__ uint32_t sm[];
    const int bid = blockIdx.x;
    const int tid = threadIdx.x;
    const int lane = tid & 31, wid = tid >> 5;
    const int g = lane >> 2, t4 = lane & 3;

    if (bid >= 128) {  // attn writers: 256 blocks = (h, mt)
        const int pb = bid - 128;
        const int h = pb >> 4, mt = pb & 15;
        const int m0 = mt * 128;
        const int r0 = wid * 16 + g;
        const size_t attn_base = (size_t)h * SQ * SQ;
        const uint32_t* kg = g_kp + h * 32 * 2048;
        uint32_t* Qp = sm;         // 4096 w
        uint32_t* Kp = sm + 4096;  // 2 x 2048 w

        {
            const uint32_t* qg = g_qp + (h * 16 + mt) * 4096;
#pragma unroll
            for (int i = 0; i < 4; i++)
                cpa16(Qp + tid * 4 + i * 1024, qg + tid * 4 + i * 1024);
        }
#pragma unroll
        for (int i = 0; i < 2; i++)
            cpa16(Kp + tid * 4 + i * 1024, kg + tid * 4 + i * 1024);
        CPA_COMMIT;
        CPA_WAIT(0);
        __syncthreads();

        uint4 qf[4];
#pragma unroll
        for (int s = 0; s < 4; s++)
            qf[s] = *(const uint4*)&Qp[frag_addr(4, wid, s, g, t4)];

        const float inv0 = 1.0f / g_rsum[h * SQ + m0 + r0];
        const float inv1 = 1.0f / g_rsum[h * SQ + m0 + r0 + 8];

        for (int tt = 0; tt < NT; tt++) {
            const int t0 = tt * 64;
            uint32_t* Kc = Kp + (tt & 1) * 2048;

            uint32_t mw[2][2];
            {
                const uint32_t* mb = g_mbits + (size_t)(tt * 2) * SQ + m0;
                mw[0][0] = mb[r0];
                mw[0][1] = mb[SQ + r0];
                mw[1][0] = mb[r0 + 8];
                mw[1][1] = mb[SQ + r0 + 8];
            }

            if (tt + 1 < NT) {
                uint32_t* Kn = Kp + ((tt + 1) & 1) * 2048;
#pragma unroll
                for (int i = 0; i < 2; i++)
                    cpa16(Kn + tid * 4 + i * 1024,
                          kg + (tt + 1) * 2048 + tid * 4 + i * 1024);
                CPA_COMMIT;
            }

            float sacc[8][4] = {};
#pragma unroll
            for (int s = 0; s < 4; s++) {
#pragma unroll
                for (int b = 0; b < 4; b++) {
                    uint4 bk = *(const uint4*)&Kc[frag_addr(4, b, s, g, t4)];
                    mma16(sacc[b * 2], qf[s].x, qf[s].y, qf[s].z, qf[s].w, bk.x, bk.z);
                    mma16(sacc[b * 2 + 1], qf[s].x, qf[s].y, qf[s].z, qf[s].w, bk.y,
                          bk.w);
                }
            }

#pragma unroll
            for (int ni = 0; ni < 8; ni++) {
                int cl = ni * 8 + 2 * t4;
                int word = ni >> 2, bit = cl & 31;
                float v00 = sacc[ni][0], v01 = sacc[ni][1];
                float v10 = sacc[ni][2], v11 = sacc[ni][3];
                uint32_t w0 = mw[0][word], w1 = mw[1][word];
                if ((w0 >> bit) & 1) v00 = -1e-7f;
                if ((w0 >> (bit + 1)) & 1) v01 = -1e-7f;
                if ((w1 >> bit) & 1) v10 = -1e-7f;
                if ((w1 >> (bit + 1)) & 1) v11 = -1e-7f;
                size_t cg = attn_base + (size_t)(m0 + r0) * SQ + t0 + cl;
                __stcs((float2*)(attn + cg),
                       make_float2(__expf(v00) * inv0, __expf(v01) * inv0));
                __stcs((float2*)(attn + cg + 8 * SQ),
                       make_float2(__expf(v10) * inv1, __expf(v11) * inv1));
            }

            if (tt + 1 < NT) {
                CPA_WAIT(0);
                __syncthreads();
            }
        }
        return;
    }

    // output projection: out = O @ Wo^T from permuted g_op/Wo tiles
    const int mt = bid >> 3, nt = bid & 7;
    const int wm = (wid & 1) * 64, wn = (wid >> 1) * 32;
    const uint32_t* At = g_op + (size_t)(mt * 16) * 4096;
    const uint32_t* Bt = g_wp + (size_t)(3 * 128 + nt * 16) * 4096;

#pragma unroll
    for (int i = 0; i < 4; i++) {
        cpa16(sm + tid * 4 + i * 1024, At + tid * 4 + i * 1024);
        cpa16(sm + 4096 + tid * 4 + i * 1024, Bt + tid * 4 + i * 1024);
    }
    CPA_COMMIT;

    float acc[4][4][4] = {};

    for (int kt = 0; kt < 16; kt++) {
        uint32_t* S = sm + (kt & 1) * 8192;
        CPA_WAIT(0);
        __syncthreads();
        if (kt + 1 < 16) {
            uint32_t* Nx = sm + ((kt + 1) & 1) * 8192;
            const uint32_t* An = At + (kt + 1) * 4096;
            const uint32_t* Bn = Bt + (kt + 1) * 4096;
#pragma unroll
            for (int i = 0; i < 4; i++) {
                cpa16(Nx + tid * 4 + i * 1024, An + tid * 4 + i * 1024);
                cpa16(Nx + 4096 + tid * 4 + i * 1024, Bn + tid * 4 + i * 1024);
            }
            CPA_COMMIT;
        }
#pragma unroll
        for (int s = 0; s < 4; s++) {
            uint4 av[4], bv[2];
#pragma unroll
            for (int mi = 0; mi < 4; mi++)
                av[mi] = *(const uint4*)&S[frag_addr(4, (wm >> 4) + mi, s, g, t4)];
#pragma unroll
            for (int bi = 0; bi < 2; bi++)
                bv[bi] = *(const uint4*)&S[4096 + frag_addr(4, (wn >> 4) + bi, s, g, t4)];
#pragma unroll
            for (int mi = 0; mi < 4; mi++)
#pragma unroll
                for (int bi = 0; bi < 2; bi++) {
                    mma16(acc[mi][bi * 2], av[mi].x, av[mi].y, av[mi].z, av[mi].w,
                          bv[bi].x, bv[bi].z);
                    mma16(acc[mi][bi * 2 + 1], av[mi].x, av[mi].y, av[mi].z, av[mi].w,
                          bv[bi].y, bv[bi].w);
                }
        }
    }

#pragma unroll
    for (int mi = 0; mi < 4; mi++)
#pragma unroll
        for (int ni = 0; ni < 4; ni++)
#pragma unroll
            for (int e = 0; e < 4; e++) {
                int row = mt * 128 + wm + mi * 16 + g + (e >> 1) * 8;
                int col = nt * 128 + wn + ni * 8 + t4 * 2 + (e & 1);
                C[(size_t)row * DM + col] = acc[mi][ni][e];
            }
}

extern "C" void kernel_launch(void* const* d_in, const int* in_sizes, int n_in,
                              void* d_out, int out_size) {
    const float* q_in = (const float*)d_in[0];
    const float* k_in = (const float*)d_in[1];
    const float* v_in = (const float*)d_in[2];
    const int* mask = (const int*)d_in[3];
    const float* Wq = (const float*)d_in[4];
    const float* Wk = (const float*)d_in[5];
    const float* Wv = (const float*)d_in[6];
    const float* Wo = (const float*)d_in[7];

    float* out = (float*)d_out;           // [S, DM]
    float* attn = out + (size_t)SQ * DM;  // [H, S, S]

    static int smem_set = 0;
    if (!smem_set) {
        cudaFuncSetAttribute(fused_pass1, cudaFuncAttributeMaxDynamicSharedMemorySize,
                             49152);
        cudaFuncSetAttribute(gemm_qkv, cudaFuncAttributeMaxDynamicSharedMemorySize,
                             65536);
        cudaFuncSetAttribute(pass2, cudaFuncAttributeMaxDynamicSharedMemorySize,
                             65536);
        smem_set = 1;
    }

    prep<<<1536, 256>>>(q_in, k_in, v_in, Wq, Wk, Wv, Wo, mask);

    dim3 gQKV(8, 16, 3);
    gemm_qkv<<<gQKV, 256, 65536>>>();

    dim3 gFused(SQ / 128, NH, 1);  // (16, 16)
    fused_pass1<<<gFused, 256, 49152>>>();

    pass2<<<128 + 256, 256, 65536>>>(out, attn);
}